// round 11
// baseline (speedup 1.0000x reference)
#include <cuda_runtime.h>

// Batched active-set (water-filling) projection — warp-per-row, single-
// aggregate secant root-find per phase.
//
// Identity: the phase-0 fixed point (lower clamps) satisfies
//     M(T) = sum_e min(y_e, T) = s0 - 512,   fill = -T
// (substituting D = M - (1024-c)T into the constraint eliminates the count).
// M is monotone concave piecewise-linear -> one-sided secant from the left
// (seeded with the exact curve point (min y, 1024*min y)) is monotone
// convergent, never overshoots. Phase 1, with lower-clamps poisoned to -INF
// in d = y-u, satisfies
//     H(T') = sum_e max(d_e, T') - n_lo*T' = s_nl - 512,   fill = -T'
// H is monotone convex -> one-sided secant from the right (seeded with the
// exact point (max d, (1024-n_lo)*max d)). Within-phase fixed points are
// path-independent, so this reproduces the reference's two-phase result.
//
// Scans are 2 instr/elem (FMNMX + FADD), one fixed-point REDUX.ADD per
// iteration; convergence when the quantized aggregate hits the target or the
// secant step collapses. Warp-private; upper in shared memory.

#define NCOLS 1024
#define EPL 32
#define WARPS_PER_BLOCK 2
#define THREADS (WARPS_PER_BLOCK * 32)

#define SCALEF   262144.0f             // 2^18
#define INVSCALE (1.0f / 262144.0f)
#define C_INT    (512 << 18)           // 512 * 2^18

__device__ __forceinline__ int fkey(float x) {
    int i = __float_as_int(x);
    return i ^ ((i >> 31) & 0x7fffffff);
}
__device__ __forceinline__ float fkinv(int k) {
    return __int_as_float(k ^ ((k >> 31) & 0x7fffffff));
}

__global__ __launch_bounds__(THREADS)
void proj_kernel(const float* __restrict__ y,
                 const float* __restrict__ upper,
                 float* __restrict__ out) {
    const int lane = threadIdx.x & 31;
    const int row  = blockIdx.x * WARPS_PER_BLOCK + (threadIdx.x >> 5);

    __shared__ float su[NCOLS];
    {
        const float4* u4 = reinterpret_cast<const float4*>(upper);
        float4*       s4 = reinterpret_cast<float4*>(su);
        #pragma unroll
        for (int k = 0; k < 4; k++)
            s4[threadIdx.x + THREADS * k] = u4[threadIdx.x + THREADS * k];
    }
    __syncthreads();   // one-time; warps independent afterwards

    const float NEG_INF = __int_as_float(0xff800000);

    float yv[EPL];
    {
        const float4* yrow = reinterpret_cast<const float4*>(y + (size_t)row * NCOLS);
        #pragma unroll
        for (int k = 0; k < 8; k++) {
            const float4 a = yrow[lane + 32 * k];
            yv[4*k+0]=a.x; yv[4*k+1]=a.y; yv[4*k+2]=a.z; yv[4*k+3]=a.w;
        }
    }

    // ---- prologue: s0 (fixed point) and min(y) ----
    int si;
    float miny;
    {
        float a0=0.f,a1=0.f,a2=0.f,a3=0.f;
        float m0=yv[0],m1=yv[1],m2=yv[2],m3=yv[3];
        #pragma unroll
        for (int e = 0; e < EPL; e += 4) {
            a0 += yv[e+0]; a1 += yv[e+1]; a2 += yv[e+2]; a3 += yv[e+3];
            m0 = fminf(m0, yv[e+0]); m1 = fminf(m1, yv[e+1]);
            m2 = fminf(m2, yv[e+2]); m3 = fminf(m3, yv[e+3]);
        }
        si = __reduce_add_sync(0xffffffffu,
              (__float2int_rn(a0*SCALEF)+__float2int_rn(a1*SCALEF))
            + (__float2int_rn(a2*SCALEF)+__float2int_rn(a3*SCALEF)));
        const int km = __reduce_min_sync(0xffffffffu,
                        fkey(fminf(fminf(m0,m1), fminf(m2,m3))));
        miny = fkinv(km);
    }

    const int TGT0 = si - C_INT;                        // (s0-512)*2^18
    float T = (float)TGT0 * (INVSCALE * (1.0f/1024.0f)); // -fill0

    // ---- phase 0: secant on M(T) = sum min(y,T), from the left ----
    {
        float prevT = miny;
        int   prevM = __float2int_rn(miny * (1024.0f * SCALEF)); // exact curve pt
        #pragma unroll 1
        for (int it = 0; it < 24; ++it) {
            float b0=0.f,b1=0.f,b2=0.f,b3=0.f;
            #pragma unroll
            for (int e = 0; e < EPL; e += 4) {
                b0 += fminf(yv[e+0], T); b1 += fminf(yv[e+1], T);
                b2 += fminf(yv[e+2], T); b3 += fminf(yv[e+3], T);
            }
            const int M = __reduce_add_sync(0xffffffffu,
                  (__float2int_rn(b0*SCALEF)+__float2int_rn(b1*SCALEF))
                + (__float2int_rn(b2*SCALEF)+__float2int_rn(b3*SCALEF)));
            if (M == TGT0) break;                 // quantized root hit
            const int den = M - prevM;
            if (den <= 0) break;                  // flat/stall -> converged
            const float dT = (float)(TGT0 - M) * (T - prevT) / (float)den;
            if (!(dT > 0.0f)) break;              // stall / overshoot guard
            prevM = M; prevT = T;
            T += dT;
        }
    }
    const float T0s = T;

    // ---- transition: d = y-u (free) / -INF (lower), n_lo, sum_lower y, max d
    int   nlo; int Di; float maxd;
    const float4* su4 = reinterpret_cast<const float4*>(su);
    {
        int   c0=0,c1=0,c2=0,c3=0;
        float s0f=0.f,s1f=0.f,s2f=0.f,s3f=0.f;
        float x0=NEG_INF,x1=NEG_INF,x2=NEG_INF,x3=NEG_INF;
        #pragma unroll
        for (int k = 0; k < 8; k++) {
            const float4 u4 = su4[lane + 32 * k];
            const float uu[4] = {u4.x, u4.y, u4.z, u4.w};
            #pragma unroll
            for (int j = 0; j < 4; j++) {
                const int e = 4 * k + j;
                const bool lo = yv[e] < T0s;
                float d = yv[e] - uu[j];
                if (j==0){ s0f += lo?yv[e]:0.f; c0+=lo; } 
                else if (j==1){ s1f += lo?yv[e]:0.f; c1+=lo; }
                else if (j==2){ s2f += lo?yv[e]:0.f; c2+=lo; }
                else          { s3f += lo?yv[e]:0.f; c3+=lo; }
                d = lo ? NEG_INF : d;
                yv[e] = d;
                if (j==0) x0 = fmaxf(x0,d); else if (j==1) x1 = fmaxf(x1,d);
                else if (j==2) x2 = fmaxf(x2,d); else x3 = fmaxf(x3,d);
            }
        }
        nlo = __reduce_add_sync(0xffffffffu, (c0+c1)+(c2+c3));
        Di  = __reduce_add_sync(0xffffffffu,
              (__float2int_rn(s0f*SCALEF)+__float2int_rn(s1f*SCALEF))
            + (__float2int_rn(s2f*SCALEF)+__float2int_rn(s3f*SCALEF)));
        const int kx = __reduce_max_sync(0xffffffffu,
                        fkey(fmaxf(fmaxf(x0,x1), fmaxf(x2,x3))));
        maxd = fkinv(kx);
    }

    // ---- phase 1: secant on H(T') = sum max(d,T') - n_lo*T', from the right
    const int   TGT1 = si - Di - C_INT;                 // (s_nl-512)*2^18
    const float nloF = (float)nlo;
    float T1 = T0s;
    if (maxd > T0s) {
        float pT = maxd;
        int   pH = __float2int_rn((1024.0f - nloF) * maxd * SCALEF); // exact pt
        #pragma unroll 1
        for (int it = 0; it < 24; ++it) {
            float b0=0.f,b1=0.f,b2=0.f,b3=0.f;
            #pragma unroll
            for (int e = 0; e < EPL; e += 4) {
                b0 += fmaxf(yv[e+0], T1); b1 += fmaxf(yv[e+1], T1);
                b2 += fmaxf(yv[e+2], T1); b3 += fmaxf(yv[e+3], T1);
            }
            const int M = __reduce_add_sync(0xffffffffu,
                  (__float2int_rn(b0*SCALEF)+__float2int_rn(b1*SCALEF))
                + (__float2int_rn(b2*SCALEF)+__float2int_rn(b3*SCALEF)));
            const int H = M - __float2int_rn(nloF * T1 * SCALEF);
            if (H == TGT1) break;                 // quantized root hit
            const int den = pH - H;               // H increasing in T'
            if (den <= 0) break;
            const float dT = (float)(TGT1 - H) * (pT - T1) / (float)den;
            if (!(dT < 0.0f)) break;              // stall guard (T' decreases)
            pH = H; pT = T1;
            T1 += dT;
        }
    }
    const float fill1 = -T1;

    // ---- epilogue: lower (-INF) -> 0; upper (d > T1) -> u; free -> d+u+fill
    float4* orow = reinterpret_cast<float4*>(out + (size_t)row * NCOLS);
    #pragma unroll
    for (int k = 0; k < 8; k++) {
        const float4 u4 = su4[lane + 32 * k];
        const float uu[4] = {u4.x, u4.y, u4.z, u4.w};
        float o4[4];
        #pragma unroll
        for (int j = 0; j < 4; j++) {
            const int e = 4 * k + j;
            const float d = yv[e];
            o4[j] = (d == NEG_INF) ? 0.0f
                  : ((d > T1) ? uu[j] : d + uu[j] + fill1);
        }
        float4 v; v.x=o4[0]; v.y=o4[1]; v.z=o4[2]; v.w=o4[3];
        orow[lane + 32 * k] = v;
    }
}

extern "C" void kernel_launch(void* const* d_in, const int* in_sizes, int n_in,
                              void* d_out, int out_size) {
    const float* y     = (const float*)d_in[0];
    const float* upper = (const float*)d_in[1];
    float*       out   = (float*)d_out;
    const int rows   = in_sizes[0] / NCOLS;                      // 2048
    const int blocks = (rows + WARPS_PER_BLOCK - 1) / WARPS_PER_BLOCK;
    proj_kernel<<<blocks, THREADS>>>(y, upper, out);
}

// round 12
// speedup vs baseline: 1.1633x; 1.1633x over previous
#include <cuda_runtime.h>

// Batched active-set (water-filling) projection — 2 warps per row (64-thread
// block), Newton two-phase (the proven R10 algorithm).
//
// Each warp owns half the row (16 elems/lane). Per iteration: 16-elem
// predicated scan, intra-warp REDUX.ADD of (count, 2^18 fixed-point sum),
// then a 2-warp combine: lane0 STS.64 partial -> one __syncthreads ->
// LDS.64 peer partial -> add. Double-buffered slots make one barrier per
// iteration sufficient. Both warps derive identical Newton state, so
// control flow is block-uniform.
//
// Phase 0: lower set {y < -fill}, fill monotone decreasing.
// Phase 1: upper set {d = y-u > -fill} over the frozen complement,
//          fill monotone increasing; lower-clamps poisoned to -INF in yv.
// upper is held in registers (16/lane). Water level via __fdividef.

#define NCOLS 1024
#define EPL 16
#define THREADS 64

#define SCALEF   262144.0f              // 2^18
#define INVSCALE (1.0f / 262144.0f)

__global__ __launch_bounds__(THREADS)
void proj_kernel(const float* __restrict__ y,
                 const float* __restrict__ upper,
                 float* __restrict__ out) {
    const int t    = threadIdx.x;
    const int wid  = t >> 5;
    const int row  = blockIdx.x;

    __shared__ int2 slot[2][2];          // [buffer][warp]

    const float NEG_INF = __int_as_float(0xff800000);

    float yv[EPL], uv[EPL];
    {
        const float4* yrow = reinterpret_cast<const float4*>(y + (size_t)row * NCOLS);
        const float4* urow = reinterpret_cast<const float4*>(upper);
        #pragma unroll
        for (int k = 0; k < 4; k++) {
            const float4 a = yrow[t + 64 * k];
            const float4 b = urow[t + 64 * k];
            yv[4*k+0]=a.x; yv[4*k+1]=a.y; yv[4*k+2]=a.z; yv[4*k+3]=a.w;
            uv[4*k+0]=b.x; uv[4*k+1]=b.y; uv[4*k+2]=b.z; uv[4*k+3]=b.w;
        }
    }

    // ---- s0 = sum(y): 4-way tree, 2x F2I, REDUX, 2-warp combine ----
    float base0;
    {
        float a0=0.f,a1=0.f,a2=0.f,a3=0.f;
        #pragma unroll
        for (int e = 0; e < EPL; e += 4) {
            a0 += yv[e+0]; a1 += yv[e+1]; a2 += yv[e+2]; a3 += yv[e+3];
        }
        const int h = __float2int_rn((a0+a1) * SCALEF)
                    + __float2int_rn((a2+a3) * SCALEF);
        const int hr = __reduce_add_sync(0xffffffffu, h);
        if ((t & 31) == 0) slot[0][wid] = make_int2(hr, 0);
        __syncthreads();
        const int si = hr + slot[0][wid ^ 1].x;
        base0 = 512.0f - (float)si * INVSCALE;
    }

    float fill = base0 * (1.0f / 1024.0f);
    int   buf  = 1;

    int   it = 0;
    float maskT0 = 0.0f;
    bool  p0conv = false;
    float cntF = 0.0f, dsF = 0.0f;

    // ---- phase 0: lower clamps (threshold scan on y) ----
    {
        int prev = 0;
        for (;;) {
            ++it;
            const float T = -fill;
            int   c0=0,c1=0;
            float d0=0.f,d1=0.f,d2=0.f,d3=0.f;
            #pragma unroll
            for (int e = 0; e < EPL; e += 4) {
                const bool p0 = yv[e+0] < T, p1 = yv[e+1] < T,
                           p2 = yv[e+2] < T, p3 = yv[e+3] < T;
                c0 += p0 + p2; c1 += p1 + p3;
                d0 += p0 ? yv[e+0] : 0.f; d1 += p1 ? yv[e+1] : 0.f;
                d2 += p2 ? yv[e+2] : 0.f; d3 += p3 ? yv[e+3] : 0.f;
            }
            const int dh = __float2int_rn((d0+d1) * SCALEF)
                         + __float2int_rn((d2+d3) * SCALEF);
            const int crh = __reduce_add_sync(0xffffffffu, c0 + c1);
            const int drh = __reduce_add_sync(0xffffffffu, dh);
            if ((t & 31) == 0) slot[buf][wid] = make_int2(crh, drh);
            __syncthreads();
            const int2 o = slot[buf][wid ^ 1];
            buf ^= 1;
            const int   cr = crh + o.x;
            const float D  = (float)(drh + o.y) * INVSCALE;

            maskT0 = T; cntF = (float)cr; dsF = D;
            if (cr == prev) { p0conv = true; break; }   // phase-advance round
            prev = cr;
            fill = __fdividef(base0 + D, fmaxf(1024.0f - (float)cr, 1.0f));
            if (it >= 32) break;                         // budget exhausted
        }
    }

    float4* orow = reinterpret_cast<float4*>(out + (size_t)row * NCOLS);

    if (p0conv && it < 32) {
        // phase transition: yv <- d = y-u (free) / -INF (lower-clamped)
        #pragma unroll
        for (int e = 0; e < EPL; e++)
            yv[e] = (yv[e] < maskT0) ? NEG_INF : (yv[e] - uv[e]);

        const float base1 = base0 + dsF;
        const float n1    = 1024.0f - cntF;

        // ---- phase 1: upper clamps (threshold scan on d) ----
        // poisoned entries: -INF > T is false -> never selected.
        float maskT1 = 0.0f;
        {
            int prev1 = 0;
            for (;;) {
                ++it;
                const float T = -fill;
                int   c0=0,c1=0;
                float d0=0.f,d1=0.f,d2=0.f,d3=0.f;
                #pragma unroll
                for (int e = 0; e < EPL; e += 4) {
                    const bool p0 = yv[e+0] > T, p1 = yv[e+1] > T,
                               p2 = yv[e+2] > T, p3 = yv[e+3] > T;
                    c0 += p0 + p2; c1 += p1 + p3;
                    d0 += p0 ? yv[e+0] : 0.f; d1 += p1 ? yv[e+1] : 0.f;
                    d2 += p2 ? yv[e+2] : 0.f; d3 += p3 ? yv[e+3] : 0.f;
                }
                const int dh = __float2int_rn((d0+d1) * SCALEF)
                             + __float2int_rn((d2+d3) * SCALEF);
                const int crh = __reduce_add_sync(0xffffffffu, c0 + c1);
                const int arh = __reduce_add_sync(0xffffffffu, dh);
                if ((t & 31) == 0) slot[buf][wid] = make_int2(crh, arh);
                __syncthreads();
                const int2 o = slot[buf][wid ^ 1];
                buf ^= 1;
                const int   cr = crh + o.x;
                const float A  = (float)(arh + o.y) * INVSCALE;

                maskT1 = T;
                if (cr == prev1) break;
                prev1 = cr;
                fill = __fdividef(base1 + A, fmaxf(n1 - (float)cr, 1.0f));
                if (it >= 32) break;
            }
        }

        // epilogue: yv holds d. lower (-INF) -> 0; upper (d > T1) -> u;
        // free -> y + fill = d + u + fill
        #pragma unroll
        for (int k = 0; k < 4; k++) {
            float o4[4];
            #pragma unroll
            for (int j = 0; j < 4; j++) {
                const int e = 4 * k + j;
                const float d = yv[e];
                o4[j] = (d == NEG_INF) ? 0.0f
                      : ((d > maskT1) ? uv[e] : d + uv[e] + fill);
            }
            float4 v; v.x=o4[0]; v.y=o4[1]; v.z=o4[2]; v.w=o4[3];
            orow[t + 64 * k] = v;
        }
    } else {
        // phase 1 never ran (budget exhausted in phase 0)
        #pragma unroll
        for (int k = 0; k < 4; k++) {
            float o4[4];
            #pragma unroll
            for (int j = 0; j < 4; j++) {
                const int e = 4 * k + j;
                o4[j] = (yv[e] < maskT0) ? 0.0f : yv[e] + fill;
            }
            float4 v; v.x=o4[0]; v.y=o4[1]; v.z=o4[2]; v.w=o4[3];
            orow[t + 64 * k] = v;
        }
    }
}

extern "C" void kernel_launch(void* const* d_in, const int* in_sizes, int n_in,
                              void* d_out, int out_size) {
    const float* y     = (const float*)d_in[0];
    const float* upper = (const float*)d_in[1];
    float*       out   = (float*)d_out;
    const int rows = in_sizes[0] / NCOLS;    // 2048
    proj_kernel<<<rows, THREADS>>>(y, upper, out);
}